// round 3
// baseline (speedup 1.0000x reference)
#include <cuda_runtime.h>
#include <math.h>

// Problem constants
#define NDIM 16
#define NSEC 16
#define NSUB 16
#define NE   256
#define NB   128
#define NSL  64
#define TAU_INV 10000.0f

// Output layout (float32, flattened tuple)
#define OFF_TZ1  0        // 64*16
#define OFF_TZ2  1024     // 64*16
#define OFF_FWD  2048     // 64*16*16
#define OFF_EQ   18432    // 1
#define OFF_ATTN 18433    // 64*272
#define OFF_ORTH 35841
#define OFF_PAR  35842
#define OFF_COM  35843
#define OFF_SPA  35844
#define OFF_SEC  35845
#define OFF_SUB  35846    // 64*16*16*16

// Scratch (static device globals: allowed)
__device__ float  g_diff[NE * NB * NDIM];   // (256,128,16)
__device__ float  g_n2[NE * NB];            // squared row norms
__device__ double g_acc[6];                 // eq, orth, par, com, spa, sec

// ---------------------------------------------------------------------------
// expm of a 16x16 matrix (scaling-and-squaring + 12-term Taylor), 256 threads.
// Reads Ain (not modified), writes R. Uses B,T0,T1 scratch.
// ---------------------------------------------------------------------------
__device__ __forceinline__ void expm16(const float* Ain, float sign,
                                       float* R, float* B, float* T0, float* T1,
                                       float* red, int* sScale, int t)
{
    int i = t >> 4, j = t & 15;
    B[t] = sign * Ain[t];
    __syncthreads();
    if (t < 16) {                       // 1-norm: max column abs-sum
        float cs = 0.f;
#pragma unroll
        for (int r = 0; r < 16; r++) cs += fabsf(B[r * 16 + t]);
        red[t] = cs;
    }
    __syncthreads();
    if (t == 0) {
        float nrm = 0.f;
#pragma unroll
        for (int r = 0; r < 16; r++) nrm = fmaxf(nrm, red[r]);
        int s = 0;
        while (nrm > 0.25f && s < 40) { nrm *= 0.5f; s++; }
        *sScale = s;
    }
    __syncthreads();
    int s = *sScale;
    float bt = B[t] * ldexpf(1.0f, -s);
    B[t] = bt;
    float racc = ((i == j) ? 1.0f : 0.0f) + bt;
    T0[t] = bt;
    __syncthreads();
    float* Tc = T0; float* Tn = T1;
    for (int k = 2; k <= 12; k++) {
        float acc = 0.f;
#pragma unroll
        for (int d = 0; d < 16; d++) acc += Tc[i * 16 + d] * B[d * 16 + j];
        acc *= (1.0f / (float)k);
        Tn[t] = acc;
        racc += acc;
        __syncthreads();
        float* tmp = Tc; Tc = Tn; Tn = tmp;
    }
    R[t] = racc;
    __syncthreads();
    for (int q = 0; q < s; q++) {
        float acc = 0.f;
#pragma unroll
        for (int d = 0; d < 16; d++) acc += R[i * 16 + d] * R[d * 16 + j];
        __syncthreads();
        R[t] = acc;
        __syncthreads();
    }
}

// Block(256)-wide reduce -> atomicAdd(acc, scale * sum)
__device__ __forceinline__ void block_reduce_atomic(float v, double scale,
                                                    double* acc, float* sred, int t)
{
#pragma unroll
    for (int o = 16; o; o >>= 1) v += __shfl_xor_sync(0xffffffffu, v, o);
    if ((t & 31) == 0) sred[t >> 5] = v;
    __syncthreads();
    if (t == 0) {
        double tot = 0.0;
        for (int w = 0; w < 8; w++) tot += (double)sred[w];
        atomicAdd(acc, tot * scale);
    }
}

// ---------------------------------------------------------------------------
__global__ void k_init()
{
    int t = threadIdx.x;
    if (t < 6) g_acc[t] = 0.0;
}

// One block per group element e: syms = expm(ge[e]); diff[e,b,:] = z[b] - z[b]@syms
__global__ __launch_bounds__(256) void k_expm_diff(const float* __restrict__ ge,
                                                   const float* __restrict__ z)
{
    __shared__ float sA[256], sR[256], sB[256], sT0[256], sT1[256];
    __shared__ float sZ[2048];
    __shared__ float red[16];
    __shared__ int   sScale;
    int t = threadIdx.x, e = blockIdx.x;
    sA[t] = ge[e * 256 + t];
    for (int idx = t; idx < 2048; idx += 256) sZ[idx] = z[idx];
    __syncthreads();
    expm16(sA, 1.0f, sR, sB, sT0, sT1, red, &sScale, t);

    int j = t & 15, b0 = t >> 4;
    for (int rr = 0; rr < 8; rr++) {
        int b = b0 + 16 * rr;
        float acc = 0.f;
#pragma unroll
        for (int d = 0; d < 16; d++) acc += sZ[b * 16 + d] * sR[d * 16 + j];
        float val = sZ[b * 16 + j] - acc;
        g_diff[e * 2048 + b * 16 + j] = val;
        float v2 = val * val;
#pragma unroll
        for (int o = 8; o; o >>= 1) v2 += __shfl_xor_sync(0xffffffffu, v2, o, 16);
        if (j == 0) g_n2[e * 128 + b] = v2;
    }
}

// parallel loss: per sector 2048x2048 gram of 16-dim rows, symmetric tiles 128x128
__global__ __launch_bounds__(256) void k_parallel()
{
    __shared__ float Pi[128 * 17], Pj[128 * 17];
    __shared__ float in2i[128], in2j[128];
    __shared__ float sred[8];
    int t = threadIdx.x;
    int s = blockIdx.x / 136;
    int p = blockIdx.x % 136;
    int ti = 0, len = 16;
    while (p >= len) { p -= len; len--; ti++; }
    int tj = ti + p;

    int rbaseI = s * 2048 + ti * 128;
    int rbaseJ = s * 2048 + tj * 128;
    for (int idx = t; idx < 2048; idx += 256) {
        int m = idx >> 4, d = idx & 15;
        Pi[m * 17 + d] = g_diff[rbaseI * 16 + idx];
        Pj[m * 17 + d] = g_diff[rbaseJ * 16 + idx];
    }
    if (t < 128) {
        in2i[t] = 1.0f / g_n2[rbaseI + t];
        in2j[t] = 1.0f / g_n2[rbaseJ + t];
    }
    __syncthreads();

    float local = 0.f;
    for (int idx = t; idx < 8192; idx += 256) {
        int m = idx >> 7, n = idx & 127;
        int m2 = m + 64;
        float a0 = 0.f, a1 = 0.f;
#pragma unroll
        for (int d = 0; d < 16; d++) {
            float pj = Pj[n * 17 + d];
            a0 += Pi[m * 17 + d] * pj;
            a1 += Pi[m2 * 17 + d] * pj;
        }
        float r0 = a0 * a0 * in2i[m]  * in2j[n];
        float r1 = a1 * a1 * in2i[m2] * in2j[n];
        local += __logf(r0 + 1e-9f) + __logf(r1 + 1e-9f);
    }
    double w = (ti == tj) ? -1.0 : -2.0;   // mean of -log; symmetry weight
    block_reduce_atomic(local, w, &g_acc[2], sred, t);
}

// orth: cross-sector gram of selected rows (sec_idx), 120 tile-pairs si<sj
__global__ __launch_bounds__(256) void k_orth(const int* __restrict__ sec_idx)
{
    __shared__ float Pi[128 * 17], Pj[128 * 17];
    __shared__ float in2i[128], in2j[128];
    __shared__ float sred[8];
    int t = threadIdx.x;
    int p = blockIdx.x;
    int si = 0, len = 15;
    while (p >= len) { p -= len; len--; si++; }
    int sj = si + 1 + p;

    int rbaseI = (si * 16 + sec_idx[si]) * 128;
    int rbaseJ = (sj * 16 + sec_idx[sj]) * 128;
    for (int idx = t; idx < 2048; idx += 256) {
        int m = idx >> 4, d = idx & 15;
        Pi[m * 17 + d] = g_diff[rbaseI * 16 + idx];
        Pj[m * 17 + d] = g_diff[rbaseJ * 16 + idx];
    }
    if (t < 128) {
        in2i[t] = 1.0f / g_n2[rbaseI + t];
        in2j[t] = 1.0f / g_n2[rbaseJ + t];
    }
    __syncthreads();

    float local = 0.f;
    for (int idx = t; idx < 8192; idx += 256) {
        int m = idx >> 7, n = idx & 127;
        int m2 = m + 64;
        float a0 = 0.f, a1 = 0.f;
#pragma unroll
        for (int d = 0; d < 16; d++) {
            float pj = Pj[n * 17 + d];
            a0 += Pi[m * 17 + d] * pj;
            a1 += Pi[m2 * 17 + d] * pj;
        }
        local += a0 * a0 * in2i[m]  * in2j[n];
        local += a1 * a1 * in2i[m2] * in2j[n];
    }
    block_reduce_atomic(local, 2.0, &g_acc[1], sred, t);
}

// sparse: per diff row (32768), (sum(d2) - max(d2))^2
__global__ __launch_bounds__(256) void k_sparse()
{
    __shared__ float sred[8];
    int t = threadIdx.x;
    int row = blockIdx.x * 256 + t;
    const float4* pr = (const float4*)(g_diff + row * 16);
    float s = 0.f, mx = 0.f;
#pragma unroll
    for (int q = 0; q < 4; q++) {
        float4 v = pr[q];
        float a = v.x * v.x, b = v.y * v.y, c = v.z * v.z, d = v.w * v.w;
        s += a + b + c + d;
        mx = fmaxf(mx, fmaxf(fmaxf(a, b), fmaxf(c, d)));
    }
    float v = s - mx;
    block_reduce_atomic(v * v, 1.0, &g_acc[4], sred, t);
}

// commut: 120 (a,b) pairs with cumsum weight (120 - q)
__global__ __launch_bounds__(256) void k_commut(const float* __restrict__ ge)
{
    __shared__ float Ga[256], Gb[256], Ha[256], Hb[256];
    __shared__ float sred[8];
    int t = threadIdx.x;
    int q = blockIdx.x;
    int p = q, a = 0, len = 15;
    while (p >= len) { p -= len; len--; a++; }
    int b = a + 1 + p;

    int k = t >> 4, j = t & 15;
    Ga[t] = ge[a * 256 + t];
    Gb[t] = ge[b * 256 + t];
    Ha[t] = ge[k * 4096 + a * 16 + j];   // ge[16k][a][j]
    Hb[t] = ge[k * 4096 + b * 16 + j];   // ge[16k][b][j]
    __syncthreads();

    int i = t >> 4;   // entry (i,j)
    float R1 = 0.f, R2 = 0.f;
#pragma unroll
    for (int kk = 0; kk < 16; kk++) {
        R1 += Ga[i * 16 + kk] * Hb[kk * 16 + j];
        R2 += Gb[i * 16 + kk] * Ha[kk * 16 + j];
    }
    float d = R1 - R2;
    block_reduce_atomic(d * d, 2.0 * (double)(120 - q), &g_acc[3], sred, t);
}

// main branch: one block per batch row b (0..63)
__global__ __launch_bounds__(256) void k_main(
    const float* __restrict__ mean, const float* __restrict__ logvar,
    const float* __restrict__ z, const float* __restrict__ ge,
    const float* __restrict__ lw, const float* __restrict__ lb,
    const float* __restrict__ gum, float* __restrict__ out)
{
    __shared__ float feat[64], probS[288], sw[16], fp[256], wv[256];
    __shared__ float z1v[16], z2v[16], lossArr[16], tz1s[16], tz2s[16];
    __shared__ float A[256], Bb[256], R[256], T0[256], T1[256];
    __shared__ float red[16];
    __shared__ int   sScale;
    int t = threadIdx.x, b = blockIdx.x;

    if (t < 16) {
        feat[t]      = mean[b * 16 + t];
        feat[16 + t] = __expf(0.5f * logvar[b * 16 + t]);
        feat[32 + t] = mean[(64 + b) * 16 + t];
        feat[48 + t] = __expf(0.5f * mean[(64 + b) * 16 + t]);   // ref uses mean (sic)
        z1v[t] = z[b * 16 + t];
        z2v[t] = z[(64 + b) * 16 + t];
    }
    __syncthreads();

    // prob = feat @ W^T + bias
    for (int c = t; c < 288; c += 256) {
        float acc = lb[c];
#pragma unroll 16
        for (int kk = 0; kk < 64; kk++) acc += feat[kk] * lw[c * 64 + kk];
        probS[c] = acc;
    }
    __syncthreads();

    if (t < 16) {
        int s = t;
        float l0 = probS[2 * s], l1 = probS[2 * s + 1];
        // p = softmax(logits)
        float m2 = fmaxf(l0, l1);
        float e0 = __expf(l0 - m2), e1 = __expf(l1 - m2);
        float inv = 1.0f / (e0 + e1);
        float p0 = e0 * inv, p1 = e1 * inv;
        // ls = log_softmax(p)  (yes, of the probabilities — replicate ref)
        float pm = fmaxf(p0, p1);
        float lse = pm + __logf(__expf(p0 - pm) + __expf(p1 - pm));
        float zd = z1v[s] - z2v[s];
        int tgt = (fabsf(zd) > 0.2f) ? 1 : 0;
        lossArr[s] = -((tgt ? p1 : p0) - lse);
        // gumbel attention with tau = 1e-4
        float g0 = gum[(b * 16 + s) * 2], g1 = gum[(b * 16 + s) * 2 + 1];
        float x0 = l0 + g0, x1 = l1 + g1;
        float mm = fmaxf(x0, x1);
        float a0 = __expf((x0 - mm) * TAU_INV);
        float a1 = __expf((x1 - mm) * TAU_INV);
        float as = a0 + a1;
        a0 /= as; a1 /= as;
        sw[s] = (a0 >= 0.5f || a1 > 0.5f) ? a1 : 0.0f;
        // fprob softmax over 16 sub-logits
        int base = 32 + s * 16;
        float mx = -1e30f;
        for (int u = 0; u < 16; u++) mx = fmaxf(mx, probS[base + u]);
        float sm = 0.f;
        for (int u = 0; u < 16; u++) sm += __expf(probS[base + u] - mx);
        float isv = 1.0f / sm;
        for (int u = 0; u < 16; u++) fp[s * 16 + u] = __expf(probS[base + u] - mx) * isv;
    }
    __syncthreads();

    if (t == 0) {
        float sl = 0.f;
        for (int s2 = 0; s2 < 16; s2++) sl += lossArr[s2];
        atomicAdd(&g_acc[5], (double)sl);
    }
    wv[t] = sw[t >> 4] * fp[t];
    if (t < 16) out[OFF_ATTN + b * 272 + t] = sw[t];
    out[OFF_ATTN + b * 272 + 16 + t] = fp[t];
    __syncthreads();

    // sub_syms and S
    {
        float Ssum = 0.f;
        for (int s2 = 0; s2 < 16; s2++) {
            float acc = 0.f;
#pragma unroll
            for (int u = 0; u < 16; u++)
                acc += wv[s2 * 16 + u] * ge[(s2 * 16 + u) * 256 + t];
            out[OFF_SUB + b * 4096 + s2 * 256 + t] = acc;
            Ssum += acc;
        }
        A[t] = Ssum;
    }
    __syncthreads();

    // fwd = expm(S)
    expm16(A, 1.0f, R, Bb, T0, T1, red, &sScale, t);
    out[OFF_FWD + b * 256 + t] = R[t];
    if (t < 16) {
        float acc = 0.f;
#pragma unroll
        for (int d = 0; d < 16; d++) acc += z1v[d] * R[d * 16 + t];
        tz1s[t] = acc;
        out[OFF_TZ1 + b * 16 + t] = acc;
    }
    __syncthreads();

    // inv = expm(-S)
    expm16(A, -1.0f, R, Bb, T0, T1, red, &sScale, t);
    if (t < 16) {
        float acc = 0.f;
#pragma unroll
        for (int d = 0; d < 16; d++) acc += z2v[d] * R[d * 16 + t];
        tz2s[t] = acc;
        out[OFF_TZ2 + b * 16 + t] = acc;
    }
    __syncthreads();

    if (t < 16) {
        float d1 = tz2s[t] - z1v[t];
        float d2 = tz1s[t] - z2v[t];
        float v = d1 * d1 + d2 * d2;
#pragma unroll
        for (int o = 8; o; o >>= 1) v += __shfl_xor_sync(0xffffu, v, o, 16);
        if (t == 0) atomicAdd(&g_acc[0], (double)v);
    }
}

__global__ void k_final(float* __restrict__ out)
{
    out[OFF_EQ]   = (float)(g_acc[0] / 1024.0);
    out[OFF_ORTH] = (float)(g_acc[1] / (2048.0 * 2048.0));
    out[OFF_PAR]  = (float)(g_acc[2] / 67108864.0);
    out[OFF_COM]  = (float)(g_acc[3] / 16777216.0);
    out[OFF_SPA]  = (float)(g_acc[4] / 32768.0);
    out[OFF_SEC]  = (float)(g_acc[5] / 64.0);
}

extern "C" void kernel_launch(void* const* d_in, const int* in_sizes, int n_in,
                              void* d_out, int out_size)
{
    (void)in_sizes; (void)n_in; (void)out_size;
    const float* mean    = (const float*)d_in[0];
    const float* logvar  = (const float*)d_in[1];
    const float* z       = (const float*)d_in[2];
    const float* ge      = (const float*)d_in[3];
    const float* lw      = (const float*)d_in[4];
    const float* lb      = (const float*)d_in[5];
    const float* gum     = (const float*)d_in[6];
    const int*   sec_idx = (const int*)d_in[7];
    float* out = (float*)d_out;

    k_init<<<1, 32>>>();
    k_expm_diff<<<256, 256>>>(ge, z);
    k_parallel<<<16 * 136, 256>>>();
    k_orth<<<120, 256>>>(sec_idx);
    k_sparse<<<128, 256>>>();
    k_commut<<<120, 256>>>(ge);
    k_main<<<64, 256>>>(mean, logvar, z, ge, lw, lb, gum, out);
    k_final<<<1, 1>>>(out);
}

// round 5
// speedup vs baseline: 1.2958x; 1.2958x over previous
#include <cuda_runtime.h>
#include <math.h>

// Problem constants
#define NDIM 16
#define NSEC 16
#define NSUB 16
#define NE   256
#define NB   128
#define NSL  64
#define TAU_INV 10000.0f

// Output layout (float32, flattened tuple)
#define OFF_TZ1  0        // 64*16
#define OFF_TZ2  1024     // 64*16
#define OFF_FWD  2048     // 64*16*16
#define OFF_EQ   18432    // 1
#define OFF_ATTN 18433    // 64*272
#define OFF_ORTH 35841
#define OFF_PAR  35842
#define OFF_COM  35843
#define OFF_SPA  35844
#define OFF_SEC  35845
#define OFF_SUB  35846    // 64*16*16*16

// Scratch (static device globals: allowed)
__device__ float  g_diff[NE * NB * NDIM];   // (256,128,16)
__device__ float  g_n2[NE * NB];            // squared row norms
__device__ double g_acc[6];                 // eq, orth, par, com, spa, sec

// ---------------------------------------------------------------------------
// expm of a 16x16 matrix (scaling-and-squaring + 12-term Taylor), 256 threads.
// ---------------------------------------------------------------------------
__device__ __forceinline__ void expm16(const float* Ain, float sign,
                                       float* R, float* B, float* T0, float* T1,
                                       float* red, int* sScale, int t)
{
    int i = t >> 4, j = t & 15;
    B[t] = sign * Ain[t];
    __syncthreads();
    if (t < 16) {                       // 1-norm: max column abs-sum
        float cs = 0.f;
#pragma unroll
        for (int r = 0; r < 16; r++) cs += fabsf(B[r * 16 + t]);
        red[t] = cs;
    }
    __syncthreads();
    if (t == 0) {
        float nrm = 0.f;
#pragma unroll
        for (int r = 0; r < 16; r++) nrm = fmaxf(nrm, red[r]);
        int s = 0;
        while (nrm > 0.25f && s < 40) { nrm *= 0.5f; s++; }
        *sScale = s;
    }
    __syncthreads();
    int s = *sScale;
    float bt = B[t] * ldexpf(1.0f, -s);
    B[t] = bt;
    float racc = ((i == j) ? 1.0f : 0.0f) + bt;
    T0[t] = bt;
    __syncthreads();
    float* Tc = T0; float* Tn = T1;
    for (int k = 2; k <= 12; k++) {
        float acc = 0.f;
#pragma unroll
        for (int d = 0; d < 16; d++) acc += Tc[i * 16 + d] * B[d * 16 + j];
        acc *= (1.0f / (float)k);
        Tn[t] = acc;
        racc += acc;
        __syncthreads();
        float* tmp = Tc; Tc = Tn; Tn = tmp;
    }
    R[t] = racc;
    __syncthreads();
    for (int q = 0; q < s; q++) {
        float acc = 0.f;
#pragma unroll
        for (int d = 0; d < 16; d++) acc += R[i * 16 + d] * R[d * 16 + j];
        __syncthreads();
        R[t] = acc;
        __syncthreads();
    }
}

// Block(256)-wide reduce -> atomicAdd(acc, scale * sum)
__device__ __forceinline__ void block_reduce_atomic(float v, double scale,
                                                    double* acc, float* sred, int t)
{
#pragma unroll
    for (int o = 16; o; o >>= 1) v += __shfl_xor_sync(0xffffffffu, v, o);
    if ((t & 31) == 0) sred[t >> 5] = v;
    __syncthreads();
    if (t == 0) {
        double tot = 0.0;
        for (int w = 0; w < 8; w++) tot += (double)sred[w];
        atomicAdd(acc, tot * scale);
    }
}

// ---------------------------------------------------------------------------
__global__ void k_init()
{
    int t = threadIdx.x;
    if (t < 6) g_acc[t] = 0.0;
}

// One block per group element e: syms = expm(ge[e]); diff[e,b,:] = z[b] - z[b]@syms
// Also fuses the 'sparse' loss: (sum(d2) - max(d2))^2 per row.
__global__ __launch_bounds__(256) void k_expm_diff(const float* __restrict__ ge,
                                                   const float* __restrict__ z)
{
    __shared__ float sA[256], sR[256], sB[256], sT0[256], sT1[256];
    __shared__ float sZ[2048];
    __shared__ float red[16];
    __shared__ float sred[8];
    __shared__ int   sScale;
    int t = threadIdx.x, e = blockIdx.x;
    sA[t] = ge[e * 256 + t];
    for (int idx = t; idx < 2048; idx += 256) sZ[idx] = z[idx];
    __syncthreads();
    expm16(sA, 1.0f, sR, sB, sT0, sT1, red, &sScale, t);

    int j = t & 15, b0 = t >> 4;
    float sparse_local = 0.f;
    for (int rr = 0; rr < 8; rr++) {
        int b = b0 + 16 * rr;
        float acc = 0.f;
#pragma unroll
        for (int d = 0; d < 16; d++) acc += sZ[b * 16 + d] * sR[d * 16 + j];
        float val = sZ[b * 16 + j] - acc;
        g_diff[e * 2048 + b * 16 + j] = val;
        float v2 = val * val;
        float sum = v2, mx = v2;
#pragma unroll
        for (int o = 8; o; o >>= 1) {
            sum += __shfl_xor_sync(0xffffffffu, sum, o, 16);
            mx = fmaxf(mx, __shfl_xor_sync(0xffffffffu, mx, o, 16));
        }
        if (j == 0) {
            g_n2[e * 128 + b] = sum;
            float sv = sum - mx;
            sparse_local += sv * sv;
        }
    }
    block_reduce_atomic(sparse_local, 1.0, &g_acc[4], sred, t);
}

// ---------------------------------------------------------------------------
// Register-tiled 128x128 Gram tile over 16-dim rows.
// Thread (mt,nt)=(t&31, t>>5): 4 m-rows in registers, stream 16 n-rows
// (broadcast LDS.128). Pi staged with stride 20 floats (conflict-free f4).
// ---------------------------------------------------------------------------
template <bool WITH_LOG>
__device__ __forceinline__ float gram_tile(const float* __restrict__ diffI,
                                           const float* __restrict__ diffJ,
                                           const float* __restrict__ n2I,
                                           const float* __restrict__ n2J,
                                           float* Pi, float* Pj,
                                           float* in2i, float* in2j, int t)
{
    for (int idx = t; idx < 2048; idx += 256) {
        int m = idx >> 4, d = idx & 15;
        Pi[m * 20 + d] = diffI[idx];
        Pj[idx]        = diffJ[idx];
    }
    if (t < 128) {
        in2i[t] = 1.0f / n2I[t];
        in2j[t] = 1.0f / n2J[t];
    }
    __syncthreads();

    int mt = t & 31, nt = t >> 5;
    int mbase = mt * 4;
    float pi[4][16], n_i[4];
#pragma unroll
    for (int r = 0; r < 4; r++) {
        const float4* pr = (const float4*)&Pi[(mbase + r) * 20];
#pragma unroll
        for (int q = 0; q < 4; q++) {
            float4 v = pr[q];
            pi[r][q * 4]     = v.x; pi[r][q * 4 + 1] = v.y;
            pi[r][q * 4 + 2] = v.z; pi[r][q * 4 + 3] = v.w;
        }
        n_i[r] = in2i[mbase + r];
    }

    float local = 0.f;
#pragma unroll
    for (int k = 0; k < 16; k++) {
        int n = nt + 8 * k;
        float pj[16];
        const float4* pr = (const float4*)&Pj[n * 16];
#pragma unroll
        for (int q = 0; q < 4; q++) {
            float4 v = pr[q];
            pj[q * 4]     = v.x; pj[q * 4 + 1] = v.y;
            pj[q * 4 + 2] = v.z; pj[q * 4 + 3] = v.w;
        }
        float nj = in2j[n];
#pragma unroll
        for (int r = 0; r < 4; r++) {
            float a = 0.f;
#pragma unroll
            for (int d = 0; d < 16; d++) a += pi[r][d] * pj[d];
            float v = a * a * n_i[r] * nj;
            if (WITH_LOG) local += __logf(v + 1e-9f);
            else          local += v;
        }
    }
    __syncthreads();   // protect shared reuse by caller if any
    return local;
}

// parallel loss: per sector 2048x2048 gram, symmetric 128x128 tiles
__global__ __launch_bounds__(256) void k_parallel()
{
    __shared__ float Pi[128 * 20], Pj[128 * 16];
    __shared__ float in2i[128], in2j[128];
    __shared__ float sred[8];
    int t = threadIdx.x;
    int s = blockIdx.x / 136;
    int p = blockIdx.x % 136;
    int ti = 0, len = 16;
    while (p >= len) { p -= len; len--; ti++; }
    int tj = ti + p;

    int rbaseI = s * 2048 + ti * 128;
    int rbaseJ = s * 2048 + tj * 128;
    float local = gram_tile<true>(g_diff + rbaseI * 16, g_diff + rbaseJ * 16,
                                  g_n2 + rbaseI, g_n2 + rbaseJ,
                                  Pi, Pj, in2i, in2j, t);
    double w = (ti == tj) ? -1.0 : -2.0;   // mean of -log; symmetry weight
    block_reduce_atomic(local, w, &g_acc[2], sred, t);
}

// orth: cross-sector gram of selected rows (sec_idx), 120 tile-pairs si<sj
__global__ __launch_bounds__(256) void k_orth(const int* __restrict__ sec_idx)
{
    __shared__ float Pi[128 * 20], Pj[128 * 16];
    __shared__ float in2i[128], in2j[128];
    __shared__ float sred[8];
    int t = threadIdx.x;
    int p = blockIdx.x;
    int si = 0, len = 15;
    while (p >= len) { p -= len; len--; si++; }
    int sj = si + 1 + p;

    int rbaseI = (si * 16 + sec_idx[si]) * 128;
    int rbaseJ = (sj * 16 + sec_idx[sj]) * 128;
    float local = gram_tile<false>(g_diff + rbaseI * 16, g_diff + rbaseJ * 16,
                                   g_n2 + rbaseI, g_n2 + rbaseJ,
                                   Pi, Pj, in2i, in2j, t);
    block_reduce_atomic(local, 2.0, &g_acc[1], sred, t);
}

// commut: 120 (a,b) pairs with cumsum weight (120 - q)
__global__ __launch_bounds__(256) void k_commut(const float* __restrict__ ge)
{
    __shared__ float Ga[256], Gb[256], Ha[256], Hb[256];
    __shared__ float sred[8];
    int t = threadIdx.x;
    int q = blockIdx.x;
    int p = q, a = 0, len = 15;
    while (p >= len) { p -= len; len--; a++; }
    int b = a + 1 + p;

    int k = t >> 4, j = t & 15;
    Ga[t] = ge[a * 256 + t];
    Gb[t] = ge[b * 256 + t];
    Ha[t] = ge[k * 4096 + a * 16 + j];   // ge[16k][a][j]
    Hb[t] = ge[k * 4096 + b * 16 + j];   // ge[16k][b][j]
    __syncthreads();

    int i = t >> 4;   // entry (i,j)
    float R1 = 0.f, R2 = 0.f;
#pragma unroll
    for (int kk = 0; kk < 16; kk++) {
        R1 += Ga[i * 16 + kk] * Hb[kk * 16 + j];
        R2 += Gb[i * 16 + kk] * Ha[kk * 16 + j];
    }
    float d = R1 - R2;
    block_reduce_atomic(d * d, 2.0 * (double)(120 - q), &g_acc[3], sred, t);
}

// main branch: one block per batch row b (0..63)
__global__ __launch_bounds__(256) void k_main(
    const float* __restrict__ mean, const float* __restrict__ logvar,
    const float* __restrict__ z, const float* __restrict__ ge,
    const float* __restrict__ lw, const float* __restrict__ lb,
    const float* __restrict__ gum, float* __restrict__ out)
{
    __shared__ float feat[64], probS[288], sw[16], fp[256], wv[256];
    __shared__ float z1v[16], z2v[16], lossArr[16], tz1s[16], tz2s[16];
    __shared__ float A[256], Bb[256], R[256], T0[256], T1[256];
    __shared__ float red[16];
    __shared__ int   sScale;
    int t = threadIdx.x, b = blockIdx.x;

    if (t < 16) {
        feat[t]      = mean[b * 16 + t];
        feat[16 + t] = __expf(0.5f * logvar[b * 16 + t]);
        feat[32 + t] = mean[(64 + b) * 16 + t];
        feat[48 + t] = __expf(0.5f * mean[(64 + b) * 16 + t]);   // ref uses mean (sic)
        z1v[t] = z[b * 16 + t];
        z2v[t] = z[(64 + b) * 16 + t];
    }
    __syncthreads();

    // prob = feat @ W^T + bias
    for (int c = t; c < 288; c += 256) {
        float acc = lb[c];
#pragma unroll 16
        for (int kk = 0; kk < 64; kk++) acc += feat[kk] * lw[c * 64 + kk];
        probS[c] = acc;
    }
    __syncthreads();

    if (t < 16) {
        int s = t;
        float l0 = probS[2 * s], l1 = probS[2 * s + 1];
        // p = softmax(logits)
        float m2 = fmaxf(l0, l1);
        float e0 = __expf(l0 - m2), e1 = __expf(l1 - m2);
        float inv = 1.0f / (e0 + e1);
        float p0 = e0 * inv, p1 = e1 * inv;
        // ls = log_softmax(p)  (of the probabilities — replicate ref)
        float pm = fmaxf(p0, p1);
        float lse = pm + __logf(__expf(p0 - pm) + __expf(p1 - pm));
        float zd = z1v[s] - z2v[s];
        int tgt = (fabsf(zd) > 0.2f) ? 1 : 0;
        lossArr[s] = -((tgt ? p1 : p0) - lse);
        // gumbel attention with tau = 1e-4
        float g0 = gum[(b * 16 + s) * 2], g1 = gum[(b * 16 + s) * 2 + 1];
        float x0 = l0 + g0, x1 = l1 + g1;
        float mm = fmaxf(x0, x1);
        float a0 = __expf((x0 - mm) * TAU_INV);
        float a1 = __expf((x1 - mm) * TAU_INV);
        float as = a0 + a1;
        a0 /= as; a1 /= as;
        sw[s] = (a0 >= 0.5f || a1 > 0.5f) ? a1 : 0.0f;
        // fprob softmax over 16 sub-logits
        int base = 32 + s * 16;
        float mx = -1e30f;
        for (int u = 0; u < 16; u++) mx = fmaxf(mx, probS[base + u]);
        float sm = 0.f;
        for (int u = 0; u < 16; u++) sm += __expf(probS[base + u] - mx);
        float isv = 1.0f / sm;
        for (int u = 0; u < 16; u++) fp[s * 16 + u] = __expf(probS[base + u] - mx) * isv;
    }
    __syncthreads();

    if (t == 0) {
        float sl = 0.f;
        for (int s2 = 0; s2 < 16; s2++) sl += lossArr[s2];
        atomicAdd(&g_acc[5], (double)sl);
    }
    wv[t] = sw[t >> 4] * fp[t];
    if (t < 16) out[OFF_ATTN + b * 272 + t] = sw[t];
    out[OFF_ATTN + b * 272 + 16 + t] = fp[t];
    __syncthreads();

    // sub_syms and S
    {
        float Ssum = 0.f;
        for (int s2 = 0; s2 < 16; s2++) {
            float acc = 0.f;
#pragma unroll
            for (int u = 0; u < 16; u++)
                acc += wv[s2 * 16 + u] * ge[(s2 * 16 + u) * 256 + t];
            out[OFF_SUB + b * 4096 + s2 * 256 + t] = acc;
            Ssum += acc;
        }
        A[t] = Ssum;
    }
    __syncthreads();

    // fwd = expm(S)
    expm16(A, 1.0f, R, Bb, T0, T1, red, &sScale, t);
    out[OFF_FWD + b * 256 + t] = R[t];
    if (t < 16) {
        float acc = 0.f;
#pragma unroll
        for (int d = 0; d < 16; d++) acc += z1v[d] * R[d * 16 + t];
        tz1s[t] = acc;
        out[OFF_TZ1 + b * 16 + t] = acc;
    }
    __syncthreads();

    // inv = expm(-S)
    expm16(A, -1.0f, R, Bb, T0, T1, red, &sScale, t);
    if (t < 16) {
        float acc = 0.f;
#pragma unroll
        for (int d = 0; d < 16; d++) acc += z2v[d] * R[d * 16 + t];
        tz2s[t] = acc;
        out[OFF_TZ2 + b * 16 + t] = acc;
    }
    __syncthreads();

    if (t < 16) {
        float d1 = tz2s[t] - z1v[t];
        float d2 = tz1s[t] - z2v[t];
        float v = d1 * d1 + d2 * d2;
#pragma unroll
        for (int o = 8; o; o >>= 1) v += __shfl_xor_sync(0xffffu, v, o, 16);
        if (t == 0) atomicAdd(&g_acc[0], (double)v);
    }
}

__global__ void k_final(float* __restrict__ out)
{
    out[OFF_EQ]   = (float)(g_acc[0] / 1024.0);
    out[OFF_ORTH] = (float)(g_acc[1] / (2048.0 * 2048.0));
    out[OFF_PAR]  = (float)(g_acc[2] / 67108864.0);
    out[OFF_COM]  = (float)(g_acc[3] / 16777216.0);
    out[OFF_SPA]  = (float)(g_acc[4] / 32768.0);
    out[OFF_SEC]  = (float)(g_acc[5] / 64.0);
}

extern "C" void kernel_launch(void* const* d_in, const int* in_sizes, int n_in,
                              void* d_out, int out_size)
{
    (void)in_sizes; (void)n_in; (void)out_size;
    const float* mean    = (const float*)d_in[0];
    const float* logvar  = (const float*)d_in[1];
    const float* z       = (const float*)d_in[2];
    const float* ge      = (const float*)d_in[3];
    const float* lw      = (const float*)d_in[4];
    const float* lb      = (const float*)d_in[5];
    const float* gum     = (const float*)d_in[6];
    const int*   sec_idx = (const int*)d_in[7];
    float* out = (float*)d_out;

    k_init<<<1, 32>>>();
    k_expm_diff<<<256, 256>>>(ge, z);
    k_parallel<<<16 * 136, 256>>>();
    k_orth<<<120, 256>>>(sec_idx);
    k_commut<<<120, 256>>>(ge);
    k_main<<<64, 256>>>(mean, logvar, z, ge, lw, lb, gum, out);
    k_final<<<1, 1>>>(out);
}

// round 7
// speedup vs baseline: 1.2992x; 1.0026x over previous
#include <cuda_runtime.h>
#include <math.h>

// Problem constants
#define NDIM 16
#define NSEC 16
#define NSUB 16
#define NE   256
#define NB   128
#define NSL  64
#define TAU_INV 10000.0f

// Output layout (float32, flattened tuple)
#define OFF_TZ1  0        // 64*16
#define OFF_TZ2  1024     // 64*16
#define OFF_FWD  2048     // 64*16*16
#define OFF_EQ   18432    // 1
#define OFF_ATTN 18433    // 64*272
#define OFF_ORTH 35841
#define OFF_PAR  35842
#define OFF_COM  35843
#define OFF_SPA  35844
#define OFF_SEC  35845
#define OFF_SUB  35846    // 64*16*16*16

typedef unsigned long long u64;

// Packed f32x2 helpers (Blackwell FFMA2 path — PTX-only)
__device__ __forceinline__ u64 f2fma(u64 a, u64 b, u64 c) {
    u64 d; asm("fma.rn.f32x2 %0,%1,%2,%3;" : "=l"(d) : "l"(a), "l"(b), "l"(c)); return d;
}
__device__ __forceinline__ u64 f2mul(u64 a, u64 b) {
    u64 d; asm("mul.rn.f32x2 %0,%1,%2;" : "=l"(d) : "l"(a), "l"(b)); return d;
}
__device__ __forceinline__ u64 f2add(u64 a, u64 b) {
    u64 d; asm("add.rn.f32x2 %0,%1,%2;" : "=l"(d) : "l"(a), "l"(b)); return d;
}
__device__ __forceinline__ u64 f2pack(float lo, float hi) {
    u64 d; asm("mov.b64 %0,{%1,%2};" : "=l"(d) : "f"(lo), "f"(hi)); return d;
}
__device__ __forceinline__ void f2unpack(float& lo, float& hi, u64 v) {
    asm("mov.b64 {%0,%1},%2;" : "=f"(lo), "=f"(hi) : "l"(v));
}

// Scratch (static device globals: allowed)
__device__ float  g_diff[NE * NB * NDIM];   // (256,128,16)
__device__ float  g_n2[NE * NB];            // squared row norms
__device__ double g_acc[6];                 // eq, orth, par, com, spa, sec

// ---------------------------------------------------------------------------
// expm of a 16x16 matrix (scaling-and-squaring + 8-term Taylor), 256 threads.
// ---------------------------------------------------------------------------
__device__ __forceinline__ void expm16(const float* Ain, float sign,
                                       float* R, float* B, float* T0, float* T1,
                                       float* red, int* sScale, int t)
{
    int i = t >> 4, j = t & 15;
    B[t] = sign * Ain[t];
    __syncthreads();
    if (t < 16) {                       // 1-norm: max column abs-sum
        float cs = 0.f;
#pragma unroll
        for (int r = 0; r < 16; r++) cs += fabsf(B[r * 16 + t]);
        red[t] = cs;
    }
    __syncthreads();
    if (t == 0) {
        float nrm = 0.f;
#pragma unroll
        for (int r = 0; r < 16; r++) nrm = fmaxf(nrm, red[r]);
        int s = 0;
        while (nrm > 0.25f && s < 40) { nrm *= 0.5f; s++; }
        *sScale = s;
    }
    __syncthreads();
    int s = *sScale;
    float bt = B[t] * ldexpf(1.0f, -s);
    B[t] = bt;
    float racc = ((i == j) ? 1.0f : 0.0f) + bt;
    T0[t] = bt;
    __syncthreads();
    float* Tc = T0; float* Tn = T1;
    for (int k = 2; k <= 8; k++) {
        float acc = 0.f;
#pragma unroll
        for (int d = 0; d < 16; d++) acc += Tc[i * 16 + d] * B[d * 16 + j];
        acc *= (1.0f / (float)k);
        Tn[t] = acc;
        racc += acc;
        __syncthreads();
        float* tmp = Tc; Tc = Tn; Tn = tmp;
    }
    R[t] = racc;
    __syncthreads();
    for (int q = 0; q < s; q++) {
        float acc = 0.f;
#pragma unroll
        for (int d = 0; d < 16; d++) acc += R[i * 16 + d] * R[d * 16 + j];
        __syncthreads();
        R[t] = acc;
        __syncthreads();
    }
}

// Block(256)-wide reduce -> atomicAdd(acc, scale * sum)
__device__ __forceinline__ void block_reduce_atomic(float v, double scale,
                                                    double* acc, float* sred, int t)
{
#pragma unroll
    for (int o = 16; o; o >>= 1) v += __shfl_xor_sync(0xffffffffu, v, o);
    if ((t & 31) == 0) sred[t >> 5] = v;
    __syncthreads();
    if (t == 0) {
        double tot = 0.0;
        for (int w = 0; w < 8; w++) tot += (double)sred[w];
        atomicAdd(acc, tot * scale);
    }
}

// ---------------------------------------------------------------------------
__global__ void k_init()
{
    int t = threadIdx.x;
    if (t < 6) g_acc[t] = 0.0;
}

// One block per group element e: syms = expm(ge[e]); diff[e,b,:] = z[b] - z[b]@syms
// Also fuses the 'sparse' loss: (sum(d2) - max(d2))^2 per row.
__global__ __launch_bounds__(256) void k_expm_diff(const float* __restrict__ ge,
                                                   const float* __restrict__ z)
{
    __shared__ float sA[256], sR[256], sB[256], sT0[256], sT1[256];
    __shared__ float sZ[2048];
    __shared__ float red[16];
    __shared__ float sred[8];
    __shared__ int   sScale;
    int t = threadIdx.x, e = blockIdx.x;
    sA[t] = ge[e * 256 + t];
    for (int idx = t; idx < 2048; idx += 256) sZ[idx] = z[idx];
    __syncthreads();
    expm16(sA, 1.0f, sR, sB, sT0, sT1, red, &sScale, t);

    int j = t & 15, b0 = t >> 4;
    float sparse_local = 0.f;
    for (int rr = 0; rr < 8; rr++) {
        int b = b0 + 16 * rr;
        float acc = 0.f;
#pragma unroll
        for (int d = 0; d < 16; d++) acc += sZ[b * 16 + d] * sR[d * 16 + j];
        float val = sZ[b * 16 + j] - acc;
        g_diff[e * 2048 + b * 16 + j] = val;
        float v2 = val * val;
        float sum = v2, mx = v2;
#pragma unroll
        for (int o = 8; o; o >>= 1) {
            sum += __shfl_xor_sync(0xffffffffu, sum, o, 16);
            mx = fmaxf(mx, __shfl_xor_sync(0xffffffffu, mx, o, 16));
        }
        if (j == 0) {
            g_n2[e * 128 + b] = sum;
            float sv = sum - mx;
            sparse_local += sv * sv;
        }
    }
    block_reduce_atomic(sparse_local, 1.0, &g_acc[4], sred, t);
}

// ---------------------------------------------------------------------------
// Register-tiled Gram tile over 16-dim rows, packed f32x2 dot products.
// Thread (mt,nt)=(t&31, t>>5): RPT m-rows in registers (packed along d),
// streams 16 n-rows via broadcast LDS.128 (reinterpreted as f32x2 pairs).
// ---------------------------------------------------------------------------
template <bool WITH_LOG, int RPT>
__device__ __forceinline__ float gram_tile(const float* __restrict__ diffI,
                                           const float* __restrict__ diffJ,
                                           const float* __restrict__ n2I,
                                           const float* __restrict__ n2J,
                                           float* Pi, float* Pj,
                                           float* in2i, float* in2j, int t)
{
    const int ROWS = 32 * RPT;
    for (int idx = t; idx < ROWS * 16; idx += 256) {
        int m = idx >> 4, d = idx & 15;
        Pi[m * 20 + d] = diffI[idx];
    }
    for (int idx = t; idx < 2048; idx += 256) Pj[idx] = diffJ[idx];
    if (t < ROWS) in2i[t] = 1.0f / n2I[t];
    if (t < 128)  in2j[t] = 1.0f / n2J[t];
    __syncthreads();

    int mt = t & 31, nt = t >> 5;
    int mbase = mt * RPT;
    u64 pi2[RPT][8];
    float n_i[RPT];
#pragma unroll
    for (int r = 0; r < RPT; r++) {
        const ulonglong2* pr = (const ulonglong2*)&Pi[(mbase + r) * 20];
#pragma unroll
        for (int q = 0; q < 4; q++) {
            ulonglong2 v = pr[q];
            pi2[r][q * 2] = v.x; pi2[r][q * 2 + 1] = v.y;
        }
        n_i[r] = in2i[mbase + r];
    }
    u64 ni2[RPT / 2];
#pragma unroll
    for (int rp = 0; rp < RPT / 2; rp++) ni2[rp] = f2pack(n_i[2 * rp], n_i[2 * rp + 1]);

    const u64 eps2 = f2pack(1e-9f, 1e-9f);
    float local = 0.f;
    u64 accv = f2pack(0.f, 0.f);
#pragma unroll
    for (int k = 0; k < 16; k++) {
        int n = nt + 8 * k;
        u64 pj2[8];
        const ulonglong2* pr = (const ulonglong2*)&Pj[n * 16];
#pragma unroll
        for (int q = 0; q < 4; q++) {
            ulonglong2 v = pr[q];
            pj2[q * 2] = v.x; pj2[q * 2 + 1] = v.y;
        }
        float nj = in2j[n];
        float a[RPT];
#pragma unroll
        for (int r = 0; r < RPT; r++) {
            u64 acc = f2pack(0.f, 0.f);
#pragma unroll
            for (int d = 0; d < 8; d++) acc = f2fma(pi2[r][d], pj2[d], acc);
            float lo, hi; f2unpack(lo, hi, acc);
            a[r] = lo + hi;
        }
        u64 nj2 = f2pack(nj, nj);
#pragma unroll
        for (int rp = 0; rp < RPT / 2; rp++) {
            u64 ap = f2pack(a[2 * rp], a[2 * rp + 1]);
            u64 v = f2mul(f2mul(f2mul(ap, ap), ni2[rp]), nj2);
            if (WITH_LOG) {
                v = f2add(v, eps2);
                float v0, v1; f2unpack(v0, v1, v);
                local += __logf(v0 * v1);
            } else {
                accv = f2add(accv, v);
            }
        }
    }
    if (!WITH_LOG) {
        float v0, v1; f2unpack(v0, v1, accv);
        local = v0 + v1;
    }
    __syncthreads();
    return local;
}

// parallel loss: per sector 2048x2048 gram, symmetric 128x128 tiles
__global__ __launch_bounds__(256) void k_parallel()
{
    __shared__ float Pi[128 * 20], Pj[128 * 16];
    __shared__ float in2i[128], in2j[128];
    __shared__ float sred[8];
    int t = threadIdx.x;
    int s = blockIdx.x / 136;
    int p = blockIdx.x % 136;
    int ti = 0, len = 16;
    while (p >= len) { p -= len; len--; ti++; }
    int tj = ti + p;

    int rbaseI = s * 2048 + ti * 128;
    int rbaseJ = s * 2048 + tj * 128;
    float local = gram_tile<true, 4>(g_diff + rbaseI * 16, g_diff + rbaseJ * 16,
                                     g_n2 + rbaseI, g_n2 + rbaseJ,
                                     Pi, Pj, in2i, in2j, t);
    double w = (ti == tj) ? -1.0 : -2.0;   // mean of -log; symmetry weight
    block_reduce_atomic(local, w, &g_acc[2], sred, t);
}

// orth: cross-sector gram of selected rows (sec_idx), 120 tile-pairs si<sj,
// each split into 2 m-halves (blockIdx.y) for latency hiding.
__global__ __launch_bounds__(256) void k_orth(const int* __restrict__ sec_idx)
{
    __shared__ float Pi[64 * 20], Pj[128 * 16];
    __shared__ float in2i[64], in2j[128];
    __shared__ float sred[8];
    int t = threadIdx.x;
    int p = blockIdx.x;
    int si = 0, len = 15;
    while (p >= len) { p -= len; len--; si++; }
    int sj = si + 1 + p;

    int rbaseI = (si * 16 + sec_idx[si]) * 128 + blockIdx.y * 64;
    int rbaseJ = (sj * 16 + sec_idx[sj]) * 128;
    float local = gram_tile<false, 2>(g_diff + rbaseI * 16, g_diff + rbaseJ * 16,
                                      g_n2 + rbaseI, g_n2 + rbaseJ,
                                      Pi, Pj, in2i, in2j, t);
    block_reduce_atomic(local, 2.0, &g_acc[1], sred, t);
}

// commut: 120 (a,b) pairs with cumsum weight (120 - q)
__global__ __launch_bounds__(256) void k_commut(const float* __restrict__ ge)
{
    __shared__ float Ga[256], Gb[256], Ha[256], Hb[256];
    __shared__ float sred[8];
    int t = threadIdx.x;
    int q = blockIdx.x;
    int p = q, a = 0, len = 15;
    while (p >= len) { p -= len; len--; a++; }
    int b = a + 1 + p;

    int k = t >> 4, j = t & 15;
    Ga[t] = ge[a * 256 + t];
    Gb[t] = ge[b * 256 + t];
    Ha[t] = ge[k * 4096 + a * 16 + j];   // ge[16k][a][j]
    Hb[t] = ge[k * 4096 + b * 16 + j];   // ge[16k][b][j]
    __syncthreads();

    int i = t >> 4;   // entry (i,j)
    float R1 = 0.f, R2 = 0.f;
#pragma unroll
    for (int kk = 0; kk < 16; kk++) {
        R1 += Ga[i * 16 + kk] * Hb[kk * 16 + j];
        R2 += Gb[i * 16 + kk] * Ha[kk * 16 + j];
    }
    float d = R1 - R2;
    block_reduce_atomic(d * d, 2.0 * (double)(120 - q), &g_acc[3], sred, t);
}

// main branch: 128 blocks. b = bid&63 selects batch row; dir = bid>>6 selects
// fwd (expm(+S), tz1, sub_syms/attn/sector-loss outputs) or inv (expm(-S), tz2).
__global__ __launch_bounds__(256) void k_main(
    const float* __restrict__ mean, const float* __restrict__ logvar,
    const float* __restrict__ z, const float* __restrict__ ge,
    const float* __restrict__ lw, const float* __restrict__ lb,
    const float* __restrict__ gum, float* __restrict__ out)
{
    __shared__ float feat[64], probS[288], sw[16], fp[256], wv[256];
    __shared__ float z1v[16], z2v[16], lossArr[16], tzs[16];
    __shared__ float A[256], Bb[256], R[256], T0[256], T1[256];
    __shared__ float red[16];
    __shared__ int   sScale;
    int t = threadIdx.x;
    int b = blockIdx.x & 63;
    int dir = blockIdx.x >> 6;

    if (t < 16) {
        feat[t]      = mean[b * 16 + t];
        feat[16 + t] = __expf(0.5f * logvar[b * 16 + t]);
        feat[32 + t] = mean[(64 + b) * 16 + t];
        feat[48 + t] = __expf(0.5f * mean[(64 + b) * 16 + t]);   // ref uses mean (sic)
        z1v[t] = z[b * 16 + t];
        z2v[t] = z[(64 + b) * 16 + t];
    }
    __syncthreads();

    // prob = feat @ W^T + bias
    for (int c = t; c < 288; c += 256) {
        float acc = lb[c];
#pragma unroll 16
        for (int kk = 0; kk < 64; kk++) acc += feat[kk] * lw[c * 64 + kk];
        probS[c] = acc;
    }
    __syncthreads();

    if (t < 16) {
        int s = t;
        float l0 = probS[2 * s], l1 = probS[2 * s + 1];
        // p = softmax(logits)
        float m2 = fmaxf(l0, l1);
        float e0 = __expf(l0 - m2), e1 = __expf(l1 - m2);
        float inv = 1.0f / (e0 + e1);
        float p0 = e0 * inv, p1 = e1 * inv;
        // ls = log_softmax(p)  (of the probabilities — replicate ref)
        float pm = fmaxf(p0, p1);
        float lse = pm + __logf(__expf(p0 - pm) + __expf(p1 - pm));
        float zd = z1v[s] - z2v[s];
        int tgt = (fabsf(zd) > 0.2f) ? 1 : 0;
        lossArr[s] = -((tgt ? p1 : p0) - lse);
        // gumbel attention with tau = 1e-4
        float g0 = gum[(b * 16 + s) * 2], g1 = gum[(b * 16 + s) * 2 + 1];
        float x0 = l0 + g0, x1 = l1 + g1;
        float mm = fmaxf(x0, x1);
        float a0 = __expf((x0 - mm) * TAU_INV);
        float a1 = __expf((x1 - mm) * TAU_INV);
        float as = a0 + a1;
        a0 /= as; a1 /= as;
        sw[s] = (a0 >= 0.5f || a1 > 0.5f) ? a1 : 0.0f;
        // fprob softmax over 16 sub-logits
        int base = 32 + s * 16;
        float mx = -1e30f;
        for (int u = 0; u < 16; u++) mx = fmaxf(mx, probS[base + u]);
        float sm = 0.f;
        for (int u = 0; u < 16; u++) sm += __expf(probS[base + u] - mx);
        float isv = 1.0f / sm;
        for (int u = 0; u < 16; u++) fp[s * 16 + u] = __expf(probS[base + u] - mx) * isv;
    }
    __syncthreads();

    if (dir == 0) {
        if (t == 0) {
            float sl = 0.f;
            for (int s2 = 0; s2 < 16; s2++) sl += lossArr[s2];
            atomicAdd(&g_acc[5], (double)sl);
        }
        if (t < 16) out[OFF_ATTN + b * 272 + t] = sw[t];
        out[OFF_ATTN + b * 272 + 16 + t] = fp[t];
    }
    wv[t] = sw[t >> 4] * fp[t];
    __syncthreads();

    // sub_syms and S
    {
        float Ssum = 0.f;
        for (int s2 = 0; s2 < 16; s2++) {
            float acc = 0.f;
#pragma unroll
            for (int u = 0; u < 16; u++)
                acc += wv[s2 * 16 + u] * ge[(s2 * 16 + u) * 256 + t];
            if (dir == 0) out[OFF_SUB + b * 4096 + s2 * 256 + t] = acc;
            Ssum += acc;
        }
        A[t] = Ssum;
    }
    __syncthreads();

    if (dir == 0) {
        // fwd = expm(S)
        expm16(A, 1.0f, R, Bb, T0, T1, red, &sScale, t);
        out[OFF_FWD + b * 256 + t] = R[t];
        if (t < 16) {
            float acc = 0.f;
#pragma unroll
            for (int d = 0; d < 16; d++) acc += z1v[d] * R[d * 16 + t];
            tzs[t] = acc;
            out[OFF_TZ1 + b * 16 + t] = acc;
        }
        __syncthreads();
        if (t < 16) {
            float d2 = tzs[t] - z2v[t];
            float v = d2 * d2;
#pragma unroll
            for (int o = 8; o; o >>= 1) v += __shfl_xor_sync(0xffffu, v, o, 16);
            if (t == 0) atomicAdd(&g_acc[0], (double)v);
        }
    } else {
        // inv = expm(-S)
        expm16(A, -1.0f, R, Bb, T0, T1, red, &sScale, t);
        if (t < 16) {
            float acc = 0.f;
#pragma unroll
            for (int d = 0; d < 16; d++) acc += z2v[d] * R[d * 16 + t];
            tzs[t] = acc;
            out[OFF_TZ2 + b * 16 + t] = acc;
        }
        __syncthreads();
        if (t < 16) {
            float d1 = tzs[t] - z1v[t];
            float v = d1 * d1;
#pragma unroll
            for (int o = 8; o; o >>= 1) v += __shfl_xor_sync(0xffffu, v, o, 16);
            if (t == 0) atomicAdd(&g_acc[0], (double)v);
        }
    }
}

__global__ void k_final(float* __restrict__ out)
{
    out[OFF_EQ]   = (float)(g_acc[0] / 1024.0);
    out[OFF_ORTH] = (float)(g_acc[1] / (2048.0 * 2048.0));
    out[OFF_PAR]  = (float)(g_acc[2] / 67108864.0);
    out[OFF_COM]  = (float)(g_acc[3] / 16777216.0);
    out[OFF_SPA]  = (float)(g_acc[4] / 32768.0);
    out[OFF_SEC]  = (float)(g_acc[5] / 64.0);
}

extern "C" void kernel_launch(void* const* d_in, const int* in_sizes, int n_in,
                              void* d_out, int out_size)
{
    (void)in_sizes; (void)n_in; (void)out_size;
    const float* mean    = (const float*)d_in[0];
    const float* logvar  = (const float*)d_in[1];
    const float* z       = (const float*)d_in[2];
    const float* ge      = (const float*)d_in[3];
    const float* lw      = (const float*)d_in[4];
    const float* lb      = (const float*)d_in[5];
    const float* gum     = (const float*)d_in[6];
    const int*   sec_idx = (const int*)d_in[7];
    float* out = (float*)d_out;

    k_init<<<1, 32>>>();
    k_expm_diff<<<256, 256>>>(ge, z);
    k_parallel<<<16 * 136, 256>>>();
    k_orth<<<dim3(120, 2), 256>>>(sec_idx);
    k_commut<<<120, 256>>>(ge);
    k_main<<<128, 256>>>(mean, logvar, z, ge, lw, lb, gum, out);
    k_final<<<1, 1>>>(out);
}

// round 8
// speedup vs baseline: 1.7348x; 1.3353x over previous
#include <cuda_runtime.h>
#include <math.h>

#define TAU_INV 10000.0f

// Output layout (float32, flattened tuple)
#define OFF_TZ1  0
#define OFF_TZ2  1024
#define OFF_FWD  2048
#define OFF_EQ   18432
#define OFF_ATTN 18433
#define OFF_ORTH 35841
#define OFF_PAR  35842
#define OFF_COM  35843
#define OFF_SPA  35844
#define OFF_SEC  35845
#define OFF_SUB  35846

typedef unsigned long long u64;

// Packed f32x2 helpers (Blackwell FFMA2 path — PTX-only)
__device__ __forceinline__ u64 f2fma(u64 a, u64 b, u64 c) {
    u64 d; asm("fma.rn.f32x2 %0,%1,%2,%3;" : "=l"(d) : "l"(a), "l"(b), "l"(c)); return d;
}
__device__ __forceinline__ u64 f2mul(u64 a, u64 b) {
    u64 d; asm("mul.rn.f32x2 %0,%1,%2;" : "=l"(d) : "l"(a), "l"(b)); return d;
}
__device__ __forceinline__ u64 f2add(u64 a, u64 b) {
    u64 d; asm("add.rn.f32x2 %0,%1,%2;" : "=l"(d) : "l"(a), "l"(b)); return d;
}
__device__ __forceinline__ u64 f2pack(float lo, float hi) {
    u64 d; asm("mov.b64 %0,{%1,%2};" : "=l"(d) : "f"(lo), "f"(hi)); return d;
}
__device__ __forceinline__ void f2unpack(float& lo, float& hi, u64 v) {
    asm("mov.b64 {%0,%1},%2;" : "=f"(lo), "=f"(hi) : "l"(v));
}

// Scratch
__device__ float  g_diff[256 * 128 * 16];
__device__ float  g_n2[256 * 128];
__device__ double g_acc[6];   // eq, orth, par, com, spa, sec

// ---------------------------------------------------------------------------
// expm of a 16x16 matrix (scaling-and-squaring + 8-term Taylor), 256 threads.
// ---------------------------------------------------------------------------
__device__ __forceinline__ void expm16(const float* Ain, float sign,
                                       float* R, float* B, float* T0, float* T1,
                                       float* red, int* sScale, int t)
{
    int i = t >> 4, j = t & 15;
    B[t] = sign * Ain[t];
    __syncthreads();
    if (t < 16) {
        float cs = 0.f;
#pragma unroll
        for (int r = 0; r < 16; r++) cs += fabsf(B[r * 16 + t]);
        red[t] = cs;
    }
    __syncthreads();
    if (t == 0) {
        float nrm = 0.f;
#pragma unroll
        for (int r = 0; r < 16; r++) nrm = fmaxf(nrm, red[r]);
        int s = 0;
        while (nrm > 0.25f && s < 40) { nrm *= 0.5f; s++; }
        *sScale = s;
    }
    __syncthreads();
    int s = *sScale;
    float bt = B[t] * ldexpf(1.0f, -s);
    B[t] = bt;
    float racc = ((i == j) ? 1.0f : 0.0f) + bt;
    T0[t] = bt;
    __syncthreads();
    float* Tc = T0; float* Tn = T1;
    for (int k = 2; k <= 8; k++) {
        float acc = 0.f;
#pragma unroll
        for (int d = 0; d < 16; d++) acc += Tc[i * 16 + d] * B[d * 16 + j];
        acc *= (1.0f / (float)k);
        Tn[t] = acc;
        racc += acc;
        __syncthreads();
        float* tmp = Tc; Tc = Tn; Tn = tmp;
    }
    R[t] = racc;
    __syncthreads();
    for (int q = 0; q < s; q++) {
        float acc = 0.f;
#pragma unroll
        for (int d = 0; d < 16; d++) acc += R[i * 16 + d] * R[d * 16 + j];
        __syncthreads();
        R[t] = acc;
        __syncthreads();
    }
}

__device__ __forceinline__ void block_reduce_atomic(float v, double scale,
                                                    double* acc, float* sred, int t)
{
#pragma unroll
    for (int o = 16; o; o >>= 1) v += __shfl_xor_sync(0xffffffffu, v, o);
    if ((t & 31) == 0) sred[t >> 5] = v;
    __syncthreads();
    if (t == 0) {
        double tot = 0.0;
        for (int w = 0; w < 8; w++) tot += (double)sred[w];
        atomicAdd(acc, tot * scale);
    }
}

// ---------------------------------------------------------------------------
__global__ void k_init()
{
    int t = threadIdx.x;
    if (t < 6) g_acc[t] = 0.0;
}

// One block per group element e. Fuses the 'sparse' loss.
__global__ __launch_bounds__(256) void k_expm_diff(const float* __restrict__ ge,
                                                   const float* __restrict__ z)
{
    __shared__ float sA[256], sR[256], sB[256], sT0[256], sT1[256];
    __shared__ float sZ[2048];
    __shared__ float red[16];
    __shared__ float sred[8];
    __shared__ int   sScale;
    int t = threadIdx.x, e = blockIdx.x;
    sA[t] = ge[e * 256 + t];
    for (int idx = t; idx < 2048; idx += 256) sZ[idx] = z[idx];
    __syncthreads();
    expm16(sA, 1.0f, sR, sB, sT0, sT1, red, &sScale, t);

    int j = t & 15, b0 = t >> 4;
    float sparse_local = 0.f;
    for (int rr = 0; rr < 8; rr++) {
        int b = b0 + 16 * rr;
        float acc = 0.f;
#pragma unroll
        for (int d = 0; d < 16; d++) acc += sZ[b * 16 + d] * sR[d * 16 + j];
        float val = sZ[b * 16 + j] - acc;
        g_diff[e * 2048 + b * 16 + j] = val;
        float v2 = val * val;
        float sum = v2, mx = v2;
#pragma unroll
        for (int o = 8; o; o >>= 1) {
            sum += __shfl_xor_sync(0xffffffffu, sum, o, 16);
            mx = fmaxf(mx, __shfl_xor_sync(0xffffffffu, mx, o, 16));
        }
        if (j == 0) {
            g_n2[e * 128 + b] = sum;
            float sv = sum - mx;
            sparse_local += sv * sv;
        }
    }
    block_reduce_atomic(sparse_local, 1.0, &g_acc[4], sred, t);
}

// ---------------------------------------------------------------------------
// Outer-product Gram over d: shared layout Pd[16][132] (d-major).
// Thread (lane=t&31, w=t>>5): m-rows lane*4..+3, n-cols w*16..+15.
// 32 independent f32x2 accumulators per thread -> ILP-bound, not latency-bound.
// ---------------------------------------------------------------------------
template <bool WITH_LOG>
__device__ __forceinline__ float gram_role(const float* __restrict__ diffI,
                                           const float* __restrict__ diffJ,
                                           const float* __restrict__ n2I,
                                           const float* __restrict__ n2J,
                                           float* sm, int t)
{
    float* Pi   = sm;            // 16*132
    float* Pj   = sm + 2112;     // 16*132
    float* in2i = sm + 4224;     // 128
    float* in2j = sm + 4352;     // 128

    for (int idx = t; idx < 2048; idx += 256) {
        int m = idx >> 4, d = idx & 15;
        Pi[d * 132 + m] = diffI[idx];
        Pj[d * 132 + m] = diffJ[idx];
    }
    if (t < 128) {
        in2i[t] = 1.0f / n2I[t];
        in2j[t] = 1.0f / n2J[t];
    }
    __syncthreads();

    int m0 = (t & 31) * 4;
    int n0 = (t >> 5) * 16;

    u64 c2[4][8];
#pragma unroll
    for (int i = 0; i < 4; i++)
#pragma unroll
        for (int jp = 0; jp < 8; jp++) c2[i][jp] = 0ull;

#pragma unroll
    for (int d = 0; d < 16; d++) {
        const float4 av = *(const float4*)&Pi[d * 132 + m0];
        const ulonglong2* bp = (const ulonglong2*)&Pj[d * 132 + n0];
        ulonglong2 b01 = bp[0], b23 = bp[1], b45 = bp[2], b67 = bp[3];
        u64 b[8] = {b01.x, b01.y, b23.x, b23.y, b45.x, b45.y, b67.x, b67.y};
        u64 p[4];
        p[0] = f2pack(av.x, av.x);
        p[1] = f2pack(av.y, av.y);
        p[2] = f2pack(av.z, av.z);
        p[3] = f2pack(av.w, av.w);
#pragma unroll
        for (int i = 0; i < 4; i++)
#pragma unroll
            for (int jp = 0; jp < 8; jp++)
                c2[i][jp] = f2fma(p[i], b[jp], c2[i][jp]);
    }

    const float4 niv = *(const float4*)&in2i[m0];
    float ni[4] = {niv.x, niv.y, niv.z, niv.w};
    const ulonglong2* njp = (const ulonglong2*)&in2j[n0];
    ulonglong2 n01 = njp[0], n23 = njp[1], n45 = njp[2], n67 = njp[3];
    u64 nj[8] = {n01.x, n01.y, n23.x, n23.y, n45.x, n45.y, n67.x, n67.y};

    const u64 eps2 = f2pack(1e-9f, 1e-9f);
    float local = 0.f;
    u64 accv = 0ull;
#pragma unroll
    for (int i = 0; i < 4; i++) {
        u64 ni2 = f2pack(ni[i], ni[i]);
        if (WITH_LOG) {
#pragma unroll
            for (int g = 0; g < 4; g++) {
                u64 va = f2mul(f2mul(f2mul(c2[i][2 * g],     c2[i][2 * g]),     ni2), nj[2 * g]);
                u64 vb = f2mul(f2mul(f2mul(c2[i][2 * g + 1], c2[i][2 * g + 1]), ni2), nj[2 * g + 1]);
                va = f2add(va, eps2);
                vb = f2add(vb, eps2);
                u64 pr = f2mul(va, vb);
                float lo, hi; f2unpack(lo, hi, pr);
                local += __logf(lo * hi);
            }
        } else {
#pragma unroll
            for (int jp = 0; jp < 8; jp++)
                accv = f2add(accv, f2mul(f2mul(f2mul(c2[i][jp], c2[i][jp]), ni2), nj[jp]));
        }
    }
    if (!WITH_LOG) {
        float lo, hi; f2unpack(lo, hi, accv);
        local = lo + hi;
    }
    __syncthreads();
    return local;
}

// ---------------------------------------------------------------------------
// Fused kernel: parallel (0..2175) | orth (2176..2295) | commut (2296..2415) |
// main (2416..2543). All roles independent; only need g_diff/g_n2 (from
// k_expm_diff) and raw inputs.
// ---------------------------------------------------------------------------
__global__ __launch_bounds__(256, 2) void k_fused(
    const int* __restrict__ sec_idx, const float* __restrict__ ge,
    const float* __restrict__ mean, const float* __restrict__ logvar,
    const float* __restrict__ z, const float* __restrict__ lw,
    const float* __restrict__ lb, const float* __restrict__ gum,
    float* __restrict__ out)
{
    __shared__ __align__(16) float sm[4488];
    int t = threadIdx.x;
    int bid = blockIdx.x;

    if (bid < 2176) {
        // ---- parallel loss: per-sector 2048x2048 Gram, symmetric 128x128 tiles
        int s = bid / 136;
        int p = bid % 136;
        int ti = 0, len = 16;
        while (p >= len) { p -= len; len--; ti++; }
        int tj = ti + p;
        int rbaseI = s * 2048 + ti * 128;
        int rbaseJ = s * 2048 + tj * 128;
        float local = gram_role<true>(g_diff + rbaseI * 16, g_diff + rbaseJ * 16,
                                      g_n2 + rbaseI, g_n2 + rbaseJ, sm, t);
        double w = (ti == tj) ? -1.0 : -2.0;
        block_reduce_atomic(local, w, &g_acc[2], sm + 4480, t);
    } else if (bid < 2296) {
        // ---- orth: cross-sector Gram of selected rows, 120 pairs si<sj
        int p = bid - 2176;
        int si = 0, len = 15;
        while (p >= len) { p -= len; len--; si++; }
        int sj = si + 1 + p;
        int rbaseI = (si * 16 + sec_idx[si]) * 128;
        int rbaseJ = (sj * 16 + sec_idx[sj]) * 128;
        float local = gram_role<false>(g_diff + rbaseI * 16, g_diff + rbaseJ * 16,
                                       g_n2 + rbaseI, g_n2 + rbaseJ, sm, t);
        block_reduce_atomic(local, 2.0, &g_acc[1], sm + 4480, t);
    } else if (bid < 2416) {
        // ---- commut: 120 (a,b) pairs, cumsum weight (120 - q)
        int q = bid - 2296;
        float* Ga = sm;        float* Gb = sm + 256;
        float* Ha = sm + 512;  float* Hb = sm + 768;
        float* sred = sm + 1024;
        int p = q, a = 0, len = 15;
        while (p >= len) { p -= len; len--; a++; }
        int b = a + 1 + p;

        int k = t >> 4, j = t & 15;
        Ga[t] = ge[a * 256 + t];
        Gb[t] = ge[b * 256 + t];
        Ha[t] = ge[k * 4096 + a * 16 + j];
        Hb[t] = ge[k * 4096 + b * 16 + j];
        __syncthreads();

        int i = t >> 4;
        float R1 = 0.f, R2 = 0.f;
#pragma unroll
        for (int kk = 0; kk < 16; kk++) {
            R1 += Ga[i * 16 + kk] * Hb[kk * 16 + j];
            R2 += Gb[i * 16 + kk] * Ha[kk * 16 + j];
        }
        float d = R1 - R2;
        block_reduce_atomic(d * d, 2.0 * (double)(120 - q), &g_acc[3], sred, t);
    } else {
        // ---- main branch: mbid&63 = batch row, mbid>>6 = fwd/inv
        int mbid = bid - 2416;
        int b = mbid & 63;
        int dir = mbid >> 6;
        float* feat    = sm;
        float* probS   = sm + 64;
        float* sw      = sm + 352;
        float* fp      = sm + 368;
        float* wv      = sm + 624;
        float* z1v     = sm + 880;
        float* z2v     = sm + 896;
        float* lossArr = sm + 912;
        float* tzs     = sm + 928;
        float* A       = sm + 944;
        float* Bb      = sm + 1200;
        float* R       = sm + 1456;
        float* T0      = sm + 1712;
        float* T1      = sm + 1968;
        float* red     = sm + 2224;
        int*   sScale  = (int*)&sm[2240];

        if (t < 16) {
            feat[t]      = mean[b * 16 + t];
            feat[16 + t] = __expf(0.5f * logvar[b * 16 + t]);
            feat[32 + t] = mean[(64 + b) * 16 + t];
            feat[48 + t] = __expf(0.5f * mean[(64 + b) * 16 + t]);   // ref uses mean (sic)
            z1v[t] = z[b * 16 + t];
            z2v[t] = z[(64 + b) * 16 + t];
        }
        __syncthreads();

        for (int c = t; c < 288; c += 256) {
            float acc = lb[c];
#pragma unroll 16
            for (int kk = 0; kk < 64; kk++) acc += feat[kk] * lw[c * 64 + kk];
            probS[c] = acc;
        }
        __syncthreads();

        if (t < 16) {
            int s = t;
            float l0 = probS[2 * s], l1 = probS[2 * s + 1];
            float m2 = fmaxf(l0, l1);
            float e0 = __expf(l0 - m2), e1 = __expf(l1 - m2);
            float inv = 1.0f / (e0 + e1);
            float p0 = e0 * inv, p1 = e1 * inv;
            float pm = fmaxf(p0, p1);
            float lse = pm + __logf(__expf(p0 - pm) + __expf(p1 - pm));
            float zd = z1v[s] - z2v[s];
            int tgt = (fabsf(zd) > 0.2f) ? 1 : 0;
            lossArr[s] = -((tgt ? p1 : p0) - lse);
            float g0 = gum[(b * 16 + s) * 2], g1 = gum[(b * 16 + s) * 2 + 1];
            float x0 = l0 + g0, x1 = l1 + g1;
            float mm = fmaxf(x0, x1);
            float a0 = __expf((x0 - mm) * TAU_INV);
            float a1 = __expf((x1 - mm) * TAU_INV);
            float as = a0 + a1;
            a0 /= as; a1 /= as;
            sw[s] = (a0 >= 0.5f || a1 > 0.5f) ? a1 : 0.0f;
            int base = 32 + s * 16;
            float mx = -1e30f;
            for (int u = 0; u < 16; u++) mx = fmaxf(mx, probS[base + u]);
            float smx = 0.f;
            for (int u = 0; u < 16; u++) smx += __expf(probS[base + u] - mx);
            float isv = 1.0f / smx;
            for (int u = 0; u < 16; u++) fp[s * 16 + u] = __expf(probS[base + u] - mx) * isv;
        }
        __syncthreads();

        if (dir == 0) {
            if (t == 0) {
                float sl = 0.f;
                for (int s2 = 0; s2 < 16; s2++) sl += lossArr[s2];
                atomicAdd(&g_acc[5], (double)sl);
            }
            if (t < 16) out[OFF_ATTN + b * 272 + t] = sw[t];
            out[OFF_ATTN + b * 272 + 16 + t] = fp[t];
        }
        wv[t] = sw[t >> 4] * fp[t];
        __syncthreads();

        {
            float Ssum = 0.f;
            for (int s2 = 0; s2 < 16; s2++) {
                float acc = 0.f;
#pragma unroll
                for (int u = 0; u < 16; u++)
                    acc += wv[s2 * 16 + u] * ge[(s2 * 16 + u) * 256 + t];
                if (dir == 0) out[OFF_SUB + b * 4096 + s2 * 256 + t] = acc;
                Ssum += acc;
            }
            A[t] = Ssum;
        }
        __syncthreads();

        if (dir == 0) {
            expm16(A, 1.0f, R, Bb, T0, T1, red, sScale, t);
            out[OFF_FWD + b * 256 + t] = R[t];
            if (t < 16) {
                float acc = 0.f;
#pragma unroll
                for (int d = 0; d < 16; d++) acc += z1v[d] * R[d * 16 + t];
                tzs[t] = acc;
                out[OFF_TZ1 + b * 16 + t] = acc;
            }
            __syncthreads();
            if (t < 16) {
                float d2 = tzs[t] - z2v[t];
                float v = d2 * d2;
#pragma unroll
                for (int o = 8; o; o >>= 1) v += __shfl_xor_sync(0xffffu, v, o, 16);
                if (t == 0) atomicAdd(&g_acc[0], (double)v);
            }
        } else {
            expm16(A, -1.0f, R, Bb, T0, T1, red, sScale, t);
            if (t < 16) {
                float acc = 0.f;
#pragma unroll
                for (int d = 0; d < 16; d++) acc += z2v[d] * R[d * 16 + t];
                tzs[t] = acc;
                out[OFF_TZ2 + b * 16 + t] = acc;
            }
            __syncthreads();
            if (t < 16) {
                float d1 = tzs[t] - z1v[t];
                float v = d1 * d1;
#pragma unroll
                for (int o = 8; o; o >>= 1) v += __shfl_xor_sync(0xffffu, v, o, 16);
                if (t == 0) atomicAdd(&g_acc[0], (double)v);
            }
        }
    }
}

__global__ void k_final(float* __restrict__ out)
{
    out[OFF_EQ]   = (float)(g_acc[0] / 1024.0);
    out[OFF_ORTH] = (float)(g_acc[1] / (2048.0 * 2048.0));
    out[OFF_PAR]  = (float)(g_acc[2] / 67108864.0);
    out[OFF_COM]  = (float)(g_acc[3] / 16777216.0);
    out[OFF_SPA]  = (float)(g_acc[4] / 32768.0);
    out[OFF_SEC]  = (float)(g_acc[5] / 64.0);
}

extern "C" void kernel_launch(void* const* d_in, const int* in_sizes, int n_in,
                              void* d_out, int out_size)
{
    (void)in_sizes; (void)n_in; (void)out_size;
    const float* mean    = (const float*)d_in[0];
    const float* logvar  = (const float*)d_in[1];
    const float* z       = (const float*)d_in[2];
    const float* ge      = (const float*)d_in[3];
    const float* lw      = (const float*)d_in[4];
    const float* lb      = (const float*)d_in[5];
    const float* gum     = (const float*)d_in[6];
    const int*   sec_idx = (const int*)d_in[7];
    float* out = (float*)d_out;

    k_init<<<1, 32>>>();
    k_expm_diff<<<256, 256>>>(ge, z);
    k_fused<<<2544, 256>>>(sec_idx, ge, mean, logvar, z, lw, lb, gum, out);
    k_final<<<1, 1>>>(out);
}